// round 6
// baseline (speedup 1.0000x reference)
#include <cuda_runtime.h>
#include <math.h>
#include <stdint.h>

#define NSEG 50000
#define MROWS 800000
#define KDIM 256   // 2*D
#define ODIM 128

__device__ int g_starts[NSEG + 1];

// Round-to-nearest tf32 (plain PTX, ok on compute_103 family target)
__device__ __forceinline__ float to_tf32(float x) {
    float r; asm("cvt.rna.tf32.f32 %0, %1;" : "=f"(r) : "f"(x)); return r;
}

// ---------------------------------------------------------------------------
// Kernel 1: segment boundary detection, 4 ids per thread (dtype probe for
// int64 vs int32: word [MROWS-1] is 0 iff ids are little-endian int64).
// ---------------------------------------------------------------------------
__global__ void boundary_kernel(const void* __restrict__ segraw) {
    int t = blockIdx.x * blockDim.x + threadIdx.x;
    int base = t * 4;
    if (base >= MROWS) return;
    const int* s32 = (const int*)segraw;
    bool is64 = (s32[MROWS - 1] == 0);
    int v[5];
    if (is64) {
        const long long* s = (const long long*)segraw;
        v[0] = (base > 0) ? (int)s[base - 1] : -1;
        longlong2 a = *(const longlong2*)&s[base];
        longlong2 b = *(const longlong2*)&s[base + 2];
        v[1] = (int)a.x; v[2] = (int)a.y; v[3] = (int)b.x; v[4] = (int)b.y;
    } else {
        v[0] = (base > 0) ? s32[base - 1] : -1;
        int4 a = *(const int4*)&s32[base];
        v[1] = a.x; v[2] = a.y; v[3] = a.z; v[4] = a.w;
    }
#pragma unroll
    for (int j = 0; j < 4; ++j)
        if (v[j + 1] != v[j]) g_starts[v[j + 1]] = base + j;
    if (base == 0) g_starts[NSEG] = MROWS;
}

// ---------------------------------------------------------------------------
// Fused kernel: pool (max|mean) 32 segments into smem, then
// out[32,128] = relu(pooled @ W^T + b) via mma.sync tf32 m16n8k8.
//
// smem: As[32][260] pooled tf32 (stride 260 -> A-frag banks 4g+l4, distinct),
//       Bs[128][20]  W chunk    (stride 20  -> B-frag banks 20g+l4 mod 32, distinct),
//       sbias[128].  Total 44 KB static.
// Warps: 8 = 2(M: m16 tile each) x 4(N: 32 cols each).
// ---------------------------------------------------------------------------
#define BM_F 32
#define BKC 16
#define F_THREADS 256

__device__ __forceinline__ void mma_tf32(float* d, const uint32_t* a, const uint32_t* b) {
    asm volatile(
        "mma.sync.aligned.m16n8k8.row.col.f32.tf32.tf32.f32 "
        "{%0,%1,%2,%3}, {%4,%5,%6,%7}, {%8,%9}, {%0,%1,%2,%3};"
        : "+f"(d[0]), "+f"(d[1]), "+f"(d[2]), "+f"(d[3])
        : "r"(a[0]), "r"(a[1]), "r"(a[2]), "r"(a[3]), "r"(b[0]), "r"(b[1]));
}

__global__ __launch_bounds__(F_THREADS) void fused_kernel(const float* __restrict__ lane,
                                                          const float* __restrict__ W,
                                                          const float* __restrict__ bias,
                                                          float* __restrict__ out) {
    __shared__ float As[BM_F][260];
    __shared__ float Bs[ODIM][20];
    __shared__ float sbias[ODIM];

    const int tid  = threadIdx.x;
    const int wid  = tid >> 5;
    const int lid  = tid & 31;
    const int g    = lid >> 2;
    const int l4   = lid & 3;
    const int bm   = blockIdx.x * BM_F;

    if (tid < ODIM) sbias[tid] = bias[tid];

    // ---------------- Phase 1: pool 4 segments per warp ----------------
#pragma unroll 1
    for (int si = 0; si < 4; ++si) {
        int s = wid + si * 8;        // local segment 0..31
        int n = bm + s;
        float4 mx = make_float4(0.f, 0.f, 0.f, 0.f);
        float4 mean = mx;
        if (n < NSEG) {
            int start = g_starts[n];
            int len   = g_starts[n + 1] - start;
            const float4* p = reinterpret_cast<const float4*>(lane)
                              + (long long)start * 32 + lid;
            float4 m0 = make_float4(-INFINITY, -INFINITY, -INFINITY, -INFINITY);
            float4 m1 = m0;
            float4 s0 = make_float4(0.f, 0.f, 0.f, 0.f);
            float4 s1 = s0;
            int r = 0;
            for (; r + 4 <= len; r += 4) {
                float4 v0 = __ldcs(p);
                float4 v1 = __ldcs(p + 32);
                float4 v2 = __ldcs(p + 64);
                float4 v3 = __ldcs(p + 96);
                p += 128;
                m0.x = fmaxf(m0.x, v0.x); s0.x += v0.x;
                m0.y = fmaxf(m0.y, v0.y); s0.y += v0.y;
                m0.z = fmaxf(m0.z, v0.z); s0.z += v0.z;
                m0.w = fmaxf(m0.w, v0.w); s0.w += v0.w;
                m1.x = fmaxf(m1.x, v1.x); s1.x += v1.x;
                m1.y = fmaxf(m1.y, v1.y); s1.y += v1.y;
                m1.z = fmaxf(m1.z, v1.z); s1.z += v1.z;
                m1.w = fmaxf(m1.w, v1.w); s1.w += v1.w;
                m0.x = fmaxf(m0.x, v2.x); s0.x += v2.x;
                m0.y = fmaxf(m0.y, v2.y); s0.y += v2.y;
                m0.z = fmaxf(m0.z, v2.z); s0.z += v2.z;
                m0.w = fmaxf(m0.w, v2.w); s0.w += v2.w;
                m1.x = fmaxf(m1.x, v3.x); s1.x += v3.x;
                m1.y = fmaxf(m1.y, v3.y); s1.y += v3.y;
                m1.z = fmaxf(m1.z, v3.z); s1.z += v3.z;
                m1.w = fmaxf(m1.w, v3.w); s1.w += v3.w;
            }
            for (; r < len; ++r) {
                float4 v = __ldcs(p);
                p += 32;
                m0.x = fmaxf(m0.x, v.x); s0.x += v.x;
                m0.y = fmaxf(m0.y, v.y); s0.y += v.y;
                m0.z = fmaxf(m0.z, v.z); s0.z += v.z;
                m0.w = fmaxf(m0.w, v.w); s0.w += v.w;
            }
            float inv = 1.0f / (float)len;
            mx.x = fmaxf(m0.x, m1.x); mean.x = (s0.x + s1.x) * inv;
            mx.y = fmaxf(m0.y, m1.y); mean.y = (s0.y + s1.y) * inv;
            mx.z = fmaxf(m0.z, m1.z); mean.z = (s0.z + s1.z) * inv;
            mx.w = fmaxf(m0.w, m1.w); mean.w = (s0.w + s1.w) * inv;
        }
        // lane lid owns dims 4*lid..4*lid+3 -> consecutive addrs, no conflicts
        As[s][4 * lid + 0] = to_tf32(mx.x);
        As[s][4 * lid + 1] = to_tf32(mx.y);
        As[s][4 * lid + 2] = to_tf32(mx.z);
        As[s][4 * lid + 3] = to_tf32(mx.w);
        As[s][128 + 4 * lid + 0] = to_tf32(mean.x);
        As[s][128 + 4 * lid + 1] = to_tf32(mean.y);
        As[s][128 + 4 * lid + 2] = to_tf32(mean.z);
        As[s][128 + 4 * lid + 3] = to_tf32(mean.w);
    }
    __syncthreads();

    // ---------------- Phase 2: GEMM 32 x 128 x 256 ----------------
    const int warpM = wid >> 2;     // 0..1  -> m16 tile at rows warpM*16
    const int warpN = wid & 3;      // 0..3  -> cols warpN*32

    float acc[4][4];
#pragma unroll
    for (int j = 0; j < 4; ++j)
#pragma unroll
        for (int c = 0; c < 4; ++c) acc[j][c] = 0.f;

#pragma unroll 1
    for (int kt = 0; kt < KDIM; kt += BKC) {
        // Stage B chunk: W[128][kt:kt+16] -> 512 float4, 2 per thread
#pragma unroll
        for (int i = 0; i < 2; ++i) {
            int idx = tid + i * 256;
            int row = idx >> 2, c4 = idx & 3;
            float4 v = *(const float4*)&W[(long long)row * KDIM + kt + c4 * 4];
            v.x = to_tf32(v.x); v.y = to_tf32(v.y); v.z = to_tf32(v.z); v.w = to_tf32(v.w);
            *(float4*)&Bs[row][c4 * 4] = v;
        }
        __syncthreads();

#pragma unroll
        for (int k8 = 0; k8 < BKC / 8; ++k8) {
            const int k0 = k8 * 8;
            uint32_t afrag[4];
            {
                int mrow = warpM * 16 + g;
                afrag[0] = __float_as_uint(As[mrow][kt + k0 + l4]);
                afrag[1] = __float_as_uint(As[mrow + 8][kt + k0 + l4]);
                afrag[2] = __float_as_uint(As[mrow][kt + k0 + l4 + 4]);
                afrag[3] = __float_as_uint(As[mrow + 8][kt + k0 + l4 + 4]);
            }
            uint32_t bfrag[4][2];
#pragma unroll
            for (int j = 0; j < 4; ++j) {
                int nrow = warpN * 32 + j * 8 + g;
                bfrag[j][0] = __float_as_uint(Bs[nrow][k0 + l4]);
                bfrag[j][1] = __float_as_uint(Bs[nrow][k0 + l4 + 4]);
            }
#pragma unroll
            for (int j = 0; j < 4; ++j)
                mma_tf32(acc[j], afrag, bfrag[j]);
        }
        __syncthreads();
    }

    // ---------------- Epilogue: bias + relu, float2 stores ----------------
    int r0 = bm + warpM * 16 + g;
#pragma unroll
    for (int j = 0; j < 4; ++j) {
        int col = warpN * 32 + j * 8 + 2 * l4;
        float bx = sbias[col], by = sbias[col + 1];
        if (r0 < NSEG) {
            float2 o;
            o.x = fmaxf(acc[j][0] + bx, 0.f);
            o.y = fmaxf(acc[j][1] + by, 0.f);
            *(float2*)&out[(long long)r0 * ODIM + col] = o;
        }
        if (r0 + 8 < NSEG) {
            float2 o;
            o.x = fmaxf(acc[j][2] + bx, 0.f);
            o.y = fmaxf(acc[j][3] + by, 0.f);
            *(float2*)&out[(long long)(r0 + 8) * ODIM + col] = o;
        }
    }
}

// ---------------------------------------------------------------------------
// Inputs (metadata order): obs_encoding (unused), lane_encoding, same_obs_mask,
// W, b. Output: float32 [NSEG, ODIM].
// ---------------------------------------------------------------------------
extern "C" void kernel_launch(void* const* d_in, const int* in_sizes, int n_in,
                              void* d_out, int out_size) {
    const float* lane = (const float*)d_in[1];
    const void*  seg  = d_in[2];
    const float* W    = (const float*)d_in[3];
    const float* bias = (const float*)d_in[4];
    float* out = (float*)d_out;

    boundary_kernel<<<(MROWS / 4 + 255) / 256, 256>>>(seg);
    fused_kernel<<<(NSEG + BM_F - 1) / BM_F, F_THREADS>>>(lane, W, bias, out);
}

// round 7
// speedup vs baseline: 1.0707x; 1.0707x over previous
#include <cuda_runtime.h>
#include <math.h>
#include <stdint.h>

#define NSEG 50000
#define NSEG_PAD 50048
#define MROWS 800000
#define KDIM 256   // 2*D
#define ODIM 128

// Scratch (device globals zero-initialized -> padded rows of g_pooled are 0)
__device__ int   g_starts[NSEG + 1];
__device__ float g_pooled[(long long)NSEG_PAD * KDIM];

// Round-to-nearest tf32 (plain PTX, supported on compute_103 family target)
__device__ __forceinline__ float to_tf32(float x) {
    float r; asm("cvt.rna.tf32.f32 %0, %1;" : "=f"(r) : "f"(x)); return r;
}

// ---------------------------------------------------------------------------
// Kernel 1: segment boundary detection, 4 ids per thread (dtype probe for
// int64 vs int32: word [MROWS-1] is 0 iff ids are little-endian int64).
// ---------------------------------------------------------------------------
__global__ void boundary_kernel(const void* __restrict__ segraw) {
    int t = blockIdx.x * blockDim.x + threadIdx.x;
    int base = t * 4;
    if (base >= MROWS) return;
    const int* s32 = (const int*)segraw;
    bool is64 = (s32[MROWS - 1] == 0);
    int v[5];
    if (is64) {
        const long long* s = (const long long*)segraw;
        v[0] = (base > 0) ? (int)s[base - 1] : -1;
        longlong2 a = *(const longlong2*)&s[base];
        longlong2 b = *(const longlong2*)&s[base + 2];
        v[1] = (int)a.x; v[2] = (int)a.y; v[3] = (int)b.x; v[4] = (int)b.y;
    } else {
        v[0] = (base > 0) ? s32[base - 1] : -1;
        int4 a = *(const int4*)&s32[base];
        v[1] = a.x; v[2] = a.y; v[3] = a.z; v[4] = a.w;
    }
#pragma unroll
    for (int j = 0; j < 4; ++j)
        if (v[j + 1] != v[j]) g_starts[v[j + 1]] = base + j;
    if (base == 0) g_starts[NSEG] = MROWS;
}

// ---------------------------------------------------------------------------
// Kernel 2: segmented max+mean pooling. One warp per segment, lane owns a
// float4 of the 128-dim row. MLP=8: eight back-to-back independent LDG.128
// per lane per main-loop iteration, four accumulator chains.
// ---------------------------------------------------------------------------
#define POOL_ACC(m, s, v) \
    m.x = fmaxf(m.x, v.x); s.x += v.x; \
    m.y = fmaxf(m.y, v.y); s.y += v.y; \
    m.z = fmaxf(m.z, v.z); s.z += v.z; \
    m.w = fmaxf(m.w, v.w); s.w += v.w;

__global__ __launch_bounds__(256) void pool_kernel(const float* __restrict__ lane) {
    int warp = threadIdx.x >> 5;
    int lid  = threadIdx.x & 31;
    int n = blockIdx.x * 8 + warp;
    if (n >= NSEG) return;
    int start = g_starts[n];
    int len   = g_starts[n + 1] - start;

    const float4* p = reinterpret_cast<const float4*>(lane) + (long long)start * 32 + lid;

    float4 m0 = make_float4(-INFINITY, -INFINITY, -INFINITY, -INFINITY);
    float4 m1 = m0, m2 = m0, m3 = m0;
    float4 s0 = make_float4(0.f, 0.f, 0.f, 0.f);
    float4 s1 = s0, s2 = s0, s3 = s0;

    int r = 0;
    for (; r + 8 <= len; r += 8) {
        float4 v0 = __ldcs(p);
        float4 v1 = __ldcs(p + 32);
        float4 v2 = __ldcs(p + 64);
        float4 v3 = __ldcs(p + 96);
        float4 v4 = __ldcs(p + 128);
        float4 v5 = __ldcs(p + 160);
        float4 v6 = __ldcs(p + 192);
        float4 v7 = __ldcs(p + 224);
        p += 256;
        POOL_ACC(m0, s0, v0)
        POOL_ACC(m1, s1, v1)
        POOL_ACC(m2, s2, v2)
        POOL_ACC(m3, s3, v3)
        POOL_ACC(m0, s0, v4)
        POOL_ACC(m1, s1, v5)
        POOL_ACC(m2, s2, v6)
        POOL_ACC(m3, s3, v7)
    }
    if (r + 4 <= len) {
        float4 v0 = __ldcs(p);
        float4 v1 = __ldcs(p + 32);
        float4 v2 = __ldcs(p + 64);
        float4 v3 = __ldcs(p + 96);
        p += 128;
        r += 4;
        POOL_ACC(m0, s0, v0)
        POOL_ACC(m1, s1, v1)
        POOL_ACC(m2, s2, v2)
        POOL_ACC(m3, s3, v3)
    }
    for (; r < len; ++r) {
        float4 v = __ldcs(p);
        p += 32;
        POOL_ACC(m0, s0, v)
    }

    float4 mx, sm;
    mx.x = fmaxf(fmaxf(m0.x, m1.x), fmaxf(m2.x, m3.x));
    mx.y = fmaxf(fmaxf(m0.y, m1.y), fmaxf(m2.y, m3.y));
    mx.z = fmaxf(fmaxf(m0.z, m1.z), fmaxf(m2.z, m3.z));
    mx.w = fmaxf(fmaxf(m0.w, m1.w), fmaxf(m2.w, m3.w));
    sm.x = (s0.x + s1.x) + (s2.x + s3.x);
    sm.y = (s0.y + s1.y) + (s2.y + s3.y);
    sm.z = (s0.z + s1.z) + (s2.z + s3.z);
    sm.w = (s0.w + s1.w) + (s2.w + s3.w);

    float inv = 1.0f / (float)len;
    float4* o = reinterpret_cast<float4*>(g_pooled + (long long)n * KDIM);
    o[lid] = mx;
    o[32 + lid] = make_float4(sm.x * inv, sm.y * inv, sm.z * inv, sm.w * inv);
}

// ---------------------------------------------------------------------------
// Kernel 3: out = relu(pooled @ W^T + b) via mma.sync tf32 (m16n8k8).
// Identical to R4/R5 (known-good, ~15-17us).
// ---------------------------------------------------------------------------
#define BM 128
#define BK 32
#define A_STRIDE 36
#define G_THREADS 256

__device__ __forceinline__ void mma_tf32(float* d, const uint32_t* a, const uint32_t* b) {
    asm volatile(
        "mma.sync.aligned.m16n8k8.row.col.f32.tf32.tf32.f32 "
        "{%0,%1,%2,%3}, {%4,%5,%6,%7}, {%8,%9}, {%0,%1,%2,%3};"
        : "+f"(d[0]), "+f"(d[1]), "+f"(d[2]), "+f"(d[3])
        : "r"(a[0]), "r"(a[1]), "r"(a[2]), "r"(a[3]), "r"(b[0]), "r"(b[1]));
}

__global__ __launch_bounds__(G_THREADS) void gemm_kernel(const float* __restrict__ W,
                                                         const float* __restrict__ bias,
                                                         float* __restrict__ out) {
    __shared__ float As[BM][A_STRIDE];
    __shared__ float Bs[ODIM][A_STRIDE];
    __shared__ float sbias[ODIM];

    const int tid = threadIdx.x;
    const int wid = tid >> 5;
    const int lane = tid & 31;
    const int g  = lane >> 2;
    const int l4 = lane & 3;
    const int warpM = wid >> 1;
    const int warpN = wid & 1;
    const int bm = blockIdx.x * BM;

    if (tid < ODIM) sbias[tid] = bias[tid];

    float acc[2][8][4];
#pragma unroll
    for (int i = 0; i < 2; ++i)
#pragma unroll
        for (int j = 0; j < 8; ++j)
#pragma unroll
            for (int c = 0; c < 4; ++c) acc[i][j][c] = 0.f;

    for (int kt = 0; kt < KDIM; kt += BK) {
#pragma unroll
        for (int i = 0; i < 4; ++i) {
            int idx = tid + i * 256;
            int row = idx >> 3, c4 = idx & 7;
            float4 v = *(const float4*)&g_pooled[(long long)(bm + row) * KDIM + kt + c4 * 4];
            v.x = to_tf32(v.x); v.y = to_tf32(v.y); v.z = to_tf32(v.z); v.w = to_tf32(v.w);
            *(float4*)&As[row][c4 * 4] = v;
        }
#pragma unroll
        for (int i = 0; i < 4; ++i) {
            int idx = tid + i * 256;
            int row = idx >> 3, c4 = idx & 7;
            float4 v = *(const float4*)&W[(long long)row * KDIM + kt + c4 * 4];
            v.x = to_tf32(v.x); v.y = to_tf32(v.y); v.z = to_tf32(v.z); v.w = to_tf32(v.w);
            *(float4*)&Bs[row][c4 * 4] = v;
        }
        __syncthreads();

#pragma unroll
        for (int k8 = 0; k8 < BK / 8; ++k8) {
            const int k0 = k8 * 8;
            uint32_t afrag[2][4];
#pragma unroll
            for (int i = 0; i < 2; ++i) {
                int mrow = warpM * 32 + i * 16 + g;
                afrag[i][0] = __float_as_uint(As[mrow][k0 + l4]);
                afrag[i][1] = __float_as_uint(As[mrow + 8][k0 + l4]);
                afrag[i][2] = __float_as_uint(As[mrow][k0 + l4 + 4]);
                afrag[i][3] = __float_as_uint(As[mrow + 8][k0 + l4 + 4]);
            }
            uint32_t bfrag[8][2];
#pragma unroll
            for (int j = 0; j < 8; ++j) {
                int nrow = warpN * 64 + j * 8 + g;
                bfrag[j][0] = __float_as_uint(Bs[nrow][k0 + l4]);
                bfrag[j][1] = __float_as_uint(Bs[nrow][k0 + l4 + 4]);
            }
#pragma unroll
            for (int i = 0; i < 2; ++i)
#pragma unroll
                for (int j = 0; j < 8; ++j)
                    mma_tf32(acc[i][j], afrag[i], bfrag[j]);
        }
        __syncthreads();
    }

#pragma unroll
    for (int i = 0; i < 2; ++i) {
        int r0 = bm + warpM * 32 + i * 16 + g;
#pragma unroll
        for (int j = 0; j < 8; ++j) {
            int col = warpN * 64 + j * 8 + 2 * l4;
            float bx = sbias[col], by = sbias[col + 1];
            if (r0 < NSEG) {
                float2 o;
                o.x = fmaxf(acc[i][j][0] + bx, 0.f);
                o.y = fmaxf(acc[i][j][1] + by, 0.f);
                *(float2*)&out[(long long)r0 * ODIM + col] = o;
            }
            if (r0 + 8 < NSEG) {
                float2 o;
                o.x = fmaxf(acc[i][j][2] + bx, 0.f);
                o.y = fmaxf(acc[i][j][3] + by, 0.f);
                *(float2*)&out[(long long)(r0 + 8) * ODIM + col] = o;
            }
        }
    }
}

// ---------------------------------------------------------------------------
// Inputs (metadata order): obs_encoding (unused), lane_encoding, same_obs_mask,
// W, b. Output: float32 [NSEG, ODIM].
// ---------------------------------------------------------------------------
extern "C" void kernel_launch(void* const* d_in, const int* in_sizes, int n_in,
                              void* d_out, int out_size) {
    const float* lane = (const float*)d_in[1];
    const void*  seg  = d_in[2];
    const float* W    = (const float*)d_in[3];
    const float* bias = (const float*)d_in[4];
    float* out = (float*)d_out;

    boundary_kernel<<<(MROWS / 4 + 255) / 256, 256>>>(seg);
    pool_kernel<<<(NSEG + 7) / 8, 256>>>(lane);
    gemm_kernel<<<(NSEG_PAD + BM - 1) / BM, G_THREADS>>>(W, bias, out);
}

// round 8
// speedup vs baseline: 1.1372x; 1.0621x over previous
#include <cuda_runtime.h>
#include <math.h>
#include <stdint.h>

#define NSEG 50000
#define NSEG_PAD 50048
#define MROWS 800000
#define KDIM 256   // 2*D
#define ODIM 128

// Scratch (device globals zero-initialized -> padded rows of g_pooled are 0)
__device__ int   g_starts[NSEG + 1];
__device__ float g_pooled[(long long)NSEG_PAD * KDIM];

// Round-to-nearest tf32 (plain PTX, supported on compute_103 family target)
__device__ __forceinline__ float to_tf32(float x) {
    float r; asm("cvt.rna.tf32.f32 %0, %1;" : "=f"(r) : "f"(x)); return r;
}

// ---------------------------------------------------------------------------
// Kernel 1: segment boundary detection, 4 ids per thread (dtype probe for
// int64 vs int32: word [MROWS-1] is 0 iff ids are little-endian int64).
// ---------------------------------------------------------------------------
__global__ void boundary_kernel(const void* __restrict__ segraw) {
    int t = blockIdx.x * blockDim.x + threadIdx.x;
    int base = t * 4;
    if (base >= MROWS) return;
    const int* s32 = (const int*)segraw;
    bool is64 = (s32[MROWS - 1] == 0);
    int v[5];
    if (is64) {
        const long long* s = (const long long*)segraw;
        v[0] = (base > 0) ? (int)s[base - 1] : -1;
        longlong2 a = *(const longlong2*)&s[base];
        longlong2 b = *(const longlong2*)&s[base + 2];
        v[1] = (int)a.x; v[2] = (int)a.y; v[3] = (int)b.x; v[4] = (int)b.y;
    } else {
        v[0] = (base > 0) ? s32[base - 1] : -1;
        int4 a = *(const int4*)&s32[base];
        v[1] = a.x; v[2] = a.y; v[3] = a.z; v[4] = a.w;
    }
#pragma unroll
    for (int j = 0; j < 4; ++j)
        if (v[j + 1] != v[j]) g_starts[v[j + 1]] = base + j;
    if (base == 0) g_starts[NSEG] = MROWS;
}

// ---------------------------------------------------------------------------
// Kernel 2: segmented max+mean pooling. One warp pools TWO adjacent segments
// simultaneously (avg segment length is only 16 rows, so cross-segment
// interleaving is the only way to keep 8 independent LDG.128 in flight per
// lane). Common-prefix loop: 4 loads per segment back-to-back; MLP-2 tails.
// ---------------------------------------------------------------------------
#define POOL_ACC(m, s, v) \
    m.x = fmaxf(m.x, v.x); s.x += v.x; \
    m.y = fmaxf(m.y, v.y); s.y += v.y; \
    m.z = fmaxf(m.z, v.z); s.z += v.z; \
    m.w = fmaxf(m.w, v.w); s.w += v.w;

__global__ __launch_bounds__(128) void pool_kernel(const float* __restrict__ lane) {
    int warp = threadIdx.x >> 5;
    int lid  = threadIdx.x & 31;
    int a = (blockIdx.x * 4 + warp) * 2;          // first of the segment pair
    if (a >= NSEG) return;                        // NSEG even -> a+1 < NSEG too
    int sa = g_starts[a];
    int ea = g_starts[a + 1];
    int eb = g_starts[a + 2];
    int lenA = ea - sa;
    int lenB = eb - ea;

    const float4* pa = reinterpret_cast<const float4*>(lane) + (long long)sa * 32 + lid;
    const float4* pb = reinterpret_cast<const float4*>(lane) + (long long)ea * 32 + lid;

    float4 mA0 = make_float4(-INFINITY, -INFINITY, -INFINITY, -INFINITY);
    float4 mA1 = mA0, mB0 = mA0, mB1 = mA0;
    float4 sA0 = make_float4(0.f, 0.f, 0.f, 0.f);
    float4 sA1 = sA0, sB0 = sA0, sB1 = sA0;

    int common = lenA < lenB ? lenA : lenB;
    int r = 0;
    for (; r + 4 <= common; r += 4) {
        float4 a0 = __ldcs(pa);
        float4 a1 = __ldcs(pa + 32);
        float4 a2 = __ldcs(pa + 64);
        float4 a3 = __ldcs(pa + 96);
        float4 b0 = __ldcs(pb);
        float4 b1 = __ldcs(pb + 32);
        float4 b2 = __ldcs(pb + 64);
        float4 b3 = __ldcs(pb + 96);
        pa += 128; pb += 128;
        POOL_ACC(mA0, sA0, a0)
        POOL_ACC(mA1, sA1, a1)
        POOL_ACC(mA0, sA0, a2)
        POOL_ACC(mA1, sA1, a3)
        POOL_ACC(mB0, sB0, b0)
        POOL_ACC(mB1, sB1, b1)
        POOL_ACC(mB0, sB0, b2)
        POOL_ACC(mB1, sB1, b3)
    }
    for (; r + 2 <= common; r += 2) {
        float4 a0 = __ldcs(pa);
        float4 a1 = __ldcs(pa + 32);
        float4 b0 = __ldcs(pb);
        float4 b1 = __ldcs(pb + 32);
        pa += 64; pb += 64;
        POOL_ACC(mA0, sA0, a0)
        POOL_ACC(mA1, sA1, a1)
        POOL_ACC(mB0, sB0, b0)
        POOL_ACC(mB1, sB1, b1)
    }
    if (r < common) {
        float4 a0 = __ldcs(pa);
        float4 b0 = __ldcs(pb);
        pa += 32; pb += 32;
        ++r;
        POOL_ACC(mA0, sA0, a0)
        POOL_ACC(mB0, sB0, b0)
    }
    // Tail of A (if lenA > common)
    {
        int t = common;
        for (; t + 2 <= lenA; t += 2) {
            float4 v0 = __ldcs(pa);
            float4 v1 = __ldcs(pa + 32);
            pa += 64;
            POOL_ACC(mA0, sA0, v0)
            POOL_ACC(mA1, sA1, v1)
        }
        if (t < lenA) {
            float4 v = __ldcs(pa);
            POOL_ACC(mA0, sA0, v)
        }
    }
    // Tail of B (if lenB > common)
    {
        int t = common;
        for (; t + 2 <= lenB; t += 2) {
            float4 v0 = __ldcs(pb);
            float4 v1 = __ldcs(pb + 32);
            pb += 64;
            POOL_ACC(mB0, sB0, v0)
            POOL_ACC(mB1, sB1, v1)
        }
        if (t < lenB) {
            float4 v = __ldcs(pb);
            POOL_ACC(mB0, sB0, v)
        }
    }

    float invA = 1.0f / (float)lenA;
    float invB = 1.0f / (float)lenB;
    float4 mxA, smA, mxB, smB;
    mxA.x = fmaxf(mA0.x, mA1.x); smA.x = (sA0.x + sA1.x) * invA;
    mxA.y = fmaxf(mA0.y, mA1.y); smA.y = (sA0.y + sA1.y) * invA;
    mxA.z = fmaxf(mA0.z, mA1.z); smA.z = (sA0.z + sA1.z) * invA;
    mxA.w = fmaxf(mA0.w, mA1.w); smA.w = (sA0.w + sA1.w) * invA;
    mxB.x = fmaxf(mB0.x, mB1.x); smB.x = (sB0.x + sB1.x) * invB;
    mxB.y = fmaxf(mB0.y, mB1.y); smB.y = (sB0.y + sB1.y) * invB;
    mxB.z = fmaxf(mB0.z, mB1.z); smB.z = (sB0.z + sB1.z) * invB;
    mxB.w = fmaxf(mB0.w, mB1.w); smB.w = (sB0.w + sB1.w) * invB;

    float4* oA = reinterpret_cast<float4*>(g_pooled + (long long)a * KDIM);
    float4* oB = reinterpret_cast<float4*>(g_pooled + (long long)(a + 1) * KDIM);
    oA[lid] = mxA;
    oA[32 + lid] = smA;
    oB[lid] = mxB;
    oB[32 + lid] = smB;
}

// ---------------------------------------------------------------------------
// Kernel 3: out = relu(pooled @ W^T + b) via mma.sync tf32 (m16n8k8).
// Identical to R4/R5 (known-good, ~15-17us).
// ---------------------------------------------------------------------------
#define BM 128
#define BK 32
#define A_STRIDE 36
#define G_THREADS 256

__device__ __forceinline__ void mma_tf32(float* d, const uint32_t* a, const uint32_t* b) {
    asm volatile(
        "mma.sync.aligned.m16n8k8.row.col.f32.tf32.tf32.f32 "
        "{%0,%1,%2,%3}, {%4,%5,%6,%7}, {%8,%9}, {%0,%1,%2,%3};"
        : "+f"(d[0]), "+f"(d[1]), "+f"(d[2]), "+f"(d[3])
        : "r"(a[0]), "r"(a[1]), "r"(a[2]), "r"(a[3]), "r"(b[0]), "r"(b[1]));
}

__global__ __launch_bounds__(G_THREADS) void gemm_kernel(const float* __restrict__ W,
                                                         const float* __restrict__ bias,
                                                         float* __restrict__ out) {
    __shared__ float As[BM][A_STRIDE];
    __shared__ float Bs[ODIM][A_STRIDE];
    __shared__ float sbias[ODIM];

    const int tid = threadIdx.x;
    const int wid = tid >> 5;
    const int lane = tid & 31;
    const int g  = lane >> 2;
    const int l4 = lane & 3;
    const int warpM = wid >> 1;
    const int warpN = wid & 1;
    const int bm = blockIdx.x * BM;

    if (tid < ODIM) sbias[tid] = bias[tid];

    float acc[2][8][4];
#pragma unroll
    for (int i = 0; i < 2; ++i)
#pragma unroll
        for (int j = 0; j < 8; ++j)
#pragma unroll
            for (int c = 0; c < 4; ++c) acc[i][j][c] = 0.f;

    for (int kt = 0; kt < KDIM; kt += BK) {
#pragma unroll
        for (int i = 0; i < 4; ++i) {
            int idx = tid + i * 256;
            int row = idx >> 3, c4 = idx & 7;
            float4 v = *(const float4*)&g_pooled[(long long)(bm + row) * KDIM + kt + c4 * 4];
            v.x = to_tf32(v.x); v.y = to_tf32(v.y); v.z = to_tf32(v.z); v.w = to_tf32(v.w);
            *(float4*)&As[row][c4 * 4] = v;
        }
#pragma unroll
        for (int i = 0; i < 4; ++i) {
            int idx = tid + i * 256;
            int row = idx >> 3, c4 = idx & 7;
            float4 v = *(const float4*)&W[(long long)row * KDIM + kt + c4 * 4];
            v.x = to_tf32(v.x); v.y = to_tf32(v.y); v.z = to_tf32(v.z); v.w = to_tf32(v.w);
            *(float4*)&Bs[row][c4 * 4] = v;
        }
        __syncthreads();

#pragma unroll
        for (int k8 = 0; k8 < BK / 8; ++k8) {
            const int k0 = k8 * 8;
            uint32_t afrag[2][4];
#pragma unroll
            for (int i = 0; i < 2; ++i) {
                int mrow = warpM * 32 + i * 16 + g;
                afrag[i][0] = __float_as_uint(As[mrow][k0 + l4]);
                afrag[i][1] = __float_as_uint(As[mrow + 8][k0 + l4]);
                afrag[i][2] = __float_as_uint(As[mrow][k0 + l4 + 4]);
                afrag[i][3] = __float_as_uint(As[mrow + 8][k0 + l4 + 4]);
            }
            uint32_t bfrag[8][2];
#pragma unroll
            for (int j = 0; j < 8; ++j) {
                int nrow = warpN * 64 + j * 8 + g;
                bfrag[j][0] = __float_as_uint(Bs[nrow][k0 + l4]);
                bfrag[j][1] = __float_as_uint(Bs[nrow][k0 + l4 + 4]);
            }
#pragma unroll
            for (int i = 0; i < 2; ++i)
#pragma unroll
                for (int j = 0; j < 8; ++j)
                    mma_tf32(acc[i][j], afrag[i], bfrag[j]);
        }
        __syncthreads();
    }

#pragma unroll
    for (int i = 0; i < 2; ++i) {
        int r0 = bm + warpM * 32 + i * 16 + g;
#pragma unroll
        for (int j = 0; j < 8; ++j) {
            int col = warpN * 64 + j * 8 + 2 * l4;
            float bx = sbias[col], by = sbias[col + 1];
            if (r0 < NSEG) {
                float2 o;
                o.x = fmaxf(acc[i][j][0] + bx, 0.f);
                o.y = fmaxf(acc[i][j][1] + by, 0.f);
                *(float2*)&out[(long long)r0 * ODIM + col] = o;
            }
            if (r0 + 8 < NSEG) {
                float2 o;
                o.x = fmaxf(acc[i][j][2] + bx, 0.f);
                o.y = fmaxf(acc[i][j][3] + by, 0.f);
                *(float2*)&out[(long long)(r0 + 8) * ODIM + col] = o;
            }
        }
    }
}

// ---------------------------------------------------------------------------
// Inputs (metadata order): obs_encoding (unused), lane_encoding, same_obs_mask,
// W, b. Output: float32 [NSEG, ODIM].
// ---------------------------------------------------------------------------
extern "C" void kernel_launch(void* const* d_in, const int* in_sizes, int n_in,
                              void* d_out, int out_size) {
    const float* lane = (const float*)d_in[1];
    const void*  seg  = d_in[2];
    const float* W    = (const float*)d_in[3];
    const float* bias = (const float*)d_in[4];
    float* out = (float*)d_out;

    boundary_kernel<<<(MROWS / 4 + 255) / 256, 256>>>(seg);
    pool_kernel<<<(NSEG / 2 + 3) / 4, 128>>>(lane);
    gemm_kernel<<<(NSEG_PAD + BM - 1) / BM, G_THREADS>>>(W, bias, out);
}

// round 9
// speedup vs baseline: 1.3615x; 1.1972x over previous
#include <cuda_runtime.h>
#include <cuda_fp16.h>
#include <math.h>
#include <stdint.h>

#define NSEG 50000
#define NSEG_PAD 50048
#define MROWS 800000
#define KDIM 256   // 2*D
#define ODIM 128

// Scratch (device globals zero-initialized -> padded rows of g_pooled_h are 0)
__device__ int    g_starts[NSEG + 1];
__device__ __half g_pooled_h[(long long)NSEG_PAD * KDIM];   // 25.6 MB
__device__ __half g_W_h[ODIM * KDIM];                       // 64 KB

// ---------------------------------------------------------------------------
// Kernel 1: segment boundary detection, 4 ids per thread (dtype probe for
// int64 vs int32: word [MROWS-1] is 0 iff ids are little-endian int64).
// ---------------------------------------------------------------------------
__global__ void boundary_kernel(const void* __restrict__ segraw) {
    int t = blockIdx.x * blockDim.x + threadIdx.x;
    int base = t * 4;
    if (base >= MROWS) return;
    const int* s32 = (const int*)segraw;
    bool is64 = (s32[MROWS - 1] == 0);
    int v[5];
    if (is64) {
        const long long* s = (const long long*)segraw;
        v[0] = (base > 0) ? (int)s[base - 1] : -1;
        longlong2 a = *(const longlong2*)&s[base];
        longlong2 b = *(const longlong2*)&s[base + 2];
        v[1] = (int)a.x; v[2] = (int)a.y; v[3] = (int)b.x; v[4] = (int)b.y;
    } else {
        v[0] = (base > 0) ? s32[base - 1] : -1;
        int4 a = *(const int4*)&s32[base];
        v[1] = a.x; v[2] = a.y; v[3] = a.z; v[4] = a.w;
    }
#pragma unroll
    for (int j = 0; j < 4; ++j)
        if (v[j + 1] != v[j]) g_starts[v[j + 1]] = base + j;
    if (base == 0) g_starts[NSEG] = MROWS;
}

// ---------------------------------------------------------------------------
// Kernel 1b: W fp32 -> fp16 (one-time, 32 blocks; independent of boundary).
// ---------------------------------------------------------------------------
__global__ void wconv_kernel(const float* __restrict__ W) {
    int t = blockIdx.x * blockDim.x + threadIdx.x;    // 0..8191
    float4 v = ((const float4*)W)[t];
    __half2 h01 = __float22half2_rn(make_float2(v.x, v.y));
    __half2 h23 = __float22half2_rn(make_float2(v.z, v.w));
    uint2 u;
    u.x = *(uint32_t*)&h01;
    u.y = *(uint32_t*)&h23;
    ((uint2*)g_W_h)[t] = u;
}

// ---------------------------------------------------------------------------
// Kernel 2: segmented max+mean pooling — EXACT R5 loop (known-good 107.3us
// config: MLP=4, 128-thread blocks, __ldcs), storing results as fp16.
// ---------------------------------------------------------------------------
__global__ void pool_kernel(const float* __restrict__ lane) {
    int warp = threadIdx.x >> 5;
    int lid  = threadIdx.x & 31;
    int n = blockIdx.x * 4 + warp;
    if (n >= NSEG) return;
    int start = g_starts[n];
    int len   = g_starts[n + 1] - start;

    const float4* p = reinterpret_cast<const float4*>(lane) + (long long)start * 32 + lid;

    float4 m0 = make_float4(-INFINITY, -INFINITY, -INFINITY, -INFINITY);
    float4 m1 = m0;
    float4 s0 = make_float4(0.f, 0.f, 0.f, 0.f);
    float4 s1 = s0;

    int r = 0;
    for (; r + 4 <= len; r += 4) {
        float4 v0 = __ldcs(p);
        float4 v1 = __ldcs(p + 32);
        float4 v2 = __ldcs(p + 64);
        float4 v3 = __ldcs(p + 96);
        p += 128;
        m0.x = fmaxf(m0.x, v0.x); s0.x += v0.x;
        m0.y = fmaxf(m0.y, v0.y); s0.y += v0.y;
        m0.z = fmaxf(m0.z, v0.z); s0.z += v0.z;
        m0.w = fmaxf(m0.w, v0.w); s0.w += v0.w;
        m1.x = fmaxf(m1.x, v1.x); s1.x += v1.x;
        m1.y = fmaxf(m1.y, v1.y); s1.y += v1.y;
        m1.z = fmaxf(m1.z, v1.z); s1.z += v1.z;
        m1.w = fmaxf(m1.w, v1.w); s1.w += v1.w;
        m0.x = fmaxf(m0.x, v2.x); s0.x += v2.x;
        m0.y = fmaxf(m0.y, v2.y); s0.y += v2.y;
        m0.z = fmaxf(m0.z, v2.z); s0.z += v2.z;
        m0.w = fmaxf(m0.w, v2.w); s0.w += v2.w;
        m1.x = fmaxf(m1.x, v3.x); s1.x += v3.x;
        m1.y = fmaxf(m1.y, v3.y); s1.y += v3.y;
        m1.z = fmaxf(m1.z, v3.z); s1.z += v3.z;
        m1.w = fmaxf(m1.w, v3.w); s1.w += v3.w;
    }
    for (; r < len; ++r) {
        float4 v = __ldcs(p);
        p += 32;
        m0.x = fmaxf(m0.x, v.x); s0.x += v.x;
        m0.y = fmaxf(m0.y, v.y); s0.y += v.y;
        m0.z = fmaxf(m0.z, v.z); s0.z += v.z;
        m0.w = fmaxf(m0.w, v.w); s0.w += v.w;
    }

    float4 mx, sm;
    mx.x = fmaxf(m0.x, m1.x); sm.x = s0.x + s1.x;
    mx.y = fmaxf(m0.y, m1.y); sm.y = s0.y + s1.y;
    mx.z = fmaxf(m0.z, m1.z); sm.z = s0.z + s1.z;
    mx.w = fmaxf(m0.w, m1.w); sm.w = s0.w + s1.w;

    float inv = 1.0f / (float)len;
    __half* row = g_pooled_h + (long long)n * KDIM;
    {
        __half2 h01 = __float22half2_rn(make_float2(mx.x, mx.y));
        __half2 h23 = __float22half2_rn(make_float2(mx.z, mx.w));
        uint2 u; u.x = *(uint32_t*)&h01; u.y = *(uint32_t*)&h23;
        ((uint2*)row)[lid] = u;
    }
    {
        __half2 h01 = __float22half2_rn(make_float2(sm.x * inv, sm.y * inv));
        __half2 h23 = __float22half2_rn(make_float2(sm.z * inv, sm.w * inv));
        uint2 u; u.x = *(uint32_t*)&h01; u.y = *(uint32_t*)&h23;
        ((uint2*)row)[32 + lid] = u;
    }
}

// ---------------------------------------------------------------------------
// Kernel 3: out = relu(pooled @ W^T + b) via mma.sync m16n8k16 fp16 (fp32
// accumulate) + ldmatrix. CTA tile 128(M) x 128(N), K staged 32 halves/stage.
// Smem rows 40 halves (80B): ldmatrix phases read 8 rows whose 16B chunks hit
// bank-groups 5r+c mod 8 — all distinct -> conflict-free.
// Warps 4(M) x 2(N); warp tile 32 x 64 = 2 m-tiles x 8 n-tiles.
// ---------------------------------------------------------------------------
#define BM 128
#define BK 32          // halves per stage
#define SSTR 40        // smem row stride in halves
#define G_THREADS 256

__device__ __forceinline__ void ldmx4(uint32_t& r0, uint32_t& r1, uint32_t& r2,
                                      uint32_t& r3, uint32_t addr) {
    asm volatile("ldmatrix.sync.aligned.m8n8.x4.shared.b16 {%0,%1,%2,%3}, [%4];"
                 : "=r"(r0), "=r"(r1), "=r"(r2), "=r"(r3) : "r"(addr));
}
__device__ __forceinline__ void mma_f16(float* d, uint32_t a0, uint32_t a1,
                                        uint32_t a2, uint32_t a3,
                                        uint32_t b0, uint32_t b1) {
    asm volatile(
        "mma.sync.aligned.m16n8k16.row.col.f32.f16.f16.f32 "
        "{%0,%1,%2,%3}, {%4,%5,%6,%7}, {%8,%9}, {%0,%1,%2,%3};"
        : "+f"(d[0]), "+f"(d[1]), "+f"(d[2]), "+f"(d[3])
        : "r"(a0), "r"(a1), "r"(a2), "r"(a3), "r"(b0), "r"(b1));
}

__global__ __launch_bounds__(G_THREADS) void gemm_kernel(const float* __restrict__ bias,
                                                         float* __restrict__ out) {
    __shared__ __align__(16) __half As[BM][SSTR];
    __shared__ __align__(16) __half Bs[ODIM][SSTR];
    __shared__ float sbias[ODIM];

    const int tid  = threadIdx.x;
    const int wid  = tid >> 5;
    const int lane = tid & 31;
    const int g    = lane >> 2;
    const int l4   = lane & 3;
    const int warpM = wid >> 1;     // 0..3
    const int warpN = wid & 1;      // 0..1
    const int bm = blockIdx.x * BM;

    if (tid < ODIM) sbias[tid] = bias[tid];

    // ldmatrix per-lane addressing: matrix j = lane/8, row-in-16 = (j&1)*8 + lane%8,
    // k offset halves = (j>>1)*8.
    const int jj = lane >> 3;
    const int rowoff = ((jj & 1) << 3) + (lane & 7);
    const int koff = (jj >> 1) << 3;

    uint32_t as_base = (uint32_t)__cvta_generic_to_shared(&As[0][0]);
    uint32_t bs_base = (uint32_t)__cvta_generic_to_shared(&Bs[0][0]);
    uint32_t aaddr[2], baddr[4];
#pragma unroll
    for (int i = 0; i < 2; ++i)
        aaddr[i] = as_base + ((warpM * 32 + i * 16 + rowoff) * SSTR + koff) * 2;
#pragma unroll
    for (int p = 0; p < 4; ++p)
        baddr[p] = bs_base + ((warpN * 64 + p * 16 + rowoff) * SSTR + koff) * 2;

    float acc[2][8][4];
#pragma unroll
    for (int i = 0; i < 2; ++i)
#pragma unroll
        for (int j = 0; j < 8; ++j)
#pragma unroll
            for (int c = 0; c < 4; ++c) acc[i][j][c] = 0.f;

    for (int kt = 0; kt < KDIM; kt += BK) {
        // Stage A: 128 rows x 32 halves = 512 uint4, 2 per thread
#pragma unroll
        for (int i = 0; i < 2; ++i) {
            int idx = tid + i * 256;
            int row = idx >> 2, c8 = idx & 3;
            uint4 v = *(const uint4*)&g_pooled_h[(long long)(bm + row) * KDIM + kt + c8 * 8];
            *(uint4*)&As[row][c8 * 8] = v;
        }
        // Stage B: W_h[128][kt:kt+32]
#pragma unroll
        for (int i = 0; i < 2; ++i) {
            int idx = tid + i * 256;
            int row = idx >> 2, c8 = idx & 3;
            uint4 v = *(const uint4*)&g_W_h[row * KDIM + kt + c8 * 8];
            *(uint4*)&Bs[row][c8 * 8] = v;
        }
        __syncthreads();

#pragma unroll
        for (int kk = 0; kk < BK / 16; ++kk) {
            const uint32_t kb = kk * 32;   // 16 halves = 32 bytes
            uint32_t a[2][4];
#pragma unroll
            for (int i = 0; i < 2; ++i)
                ldmx4(a[i][0], a[i][1], a[i][2], a[i][3], aaddr[i] + kb);
            uint32_t b[4][4];
#pragma unroll
            for (int p = 0; p < 4; ++p)
                ldmx4(b[p][0], b[p][1], b[p][2], b[p][3], baddr[p] + kb);
#pragma unroll
            for (int i = 0; i < 2; ++i)
#pragma unroll
                for (int j = 0; j < 8; ++j) {
                    int p = j >> 1, o = j & 1;     // even tile: regs {0,2}; odd: {1,3}
                    mma_f16(acc[i][j], a[i][0], a[i][1], a[i][2], a[i][3],
                            b[p][o], b[p][o + 2]);
                }
        }
        __syncthreads();
    }

    // Epilogue: bias + relu, float2 stores.
#pragma unroll
    for (int i = 0; i < 2; ++i) {
        int r0 = bm + warpM * 32 + i * 16 + g;
#pragma unroll
        for (int j = 0; j < 8; ++j) {
            int col = warpN * 64 + j * 8 + 2 * l4;
            float bx = sbias[col], by = sbias[col + 1];
            if (r0 < NSEG) {
                float2 o;
                o.x = fmaxf(acc[i][j][0] + bx, 0.f);
                o.y = fmaxf(acc[i][j][1] + by, 0.f);
                *(float2*)&out[(long long)r0 * ODIM + col] = o;
            }
            if (r0 + 8 < NSEG) {
                float2 o;
                o.x = fmaxf(acc[i][j][2] + bx, 0.f);
                o.y = fmaxf(acc[i][j][3] + by, 0.f);
                *(float2*)&out[(long long)(r0 + 8) * ODIM + col] = o;
            }
        }
    }
}

// ---------------------------------------------------------------------------
// Inputs (metadata order): obs_encoding (unused), lane_encoding, same_obs_mask,
// W, b. Output: float32 [NSEG, ODIM].
// ---------------------------------------------------------------------------
extern "C" void kernel_launch(void* const* d_in, const int* in_sizes, int n_in,
                              void* d_out, int out_size) {
    const float* lane = (const float*)d_in[1];
    const void*  seg  = d_in[2];
    const float* W    = (const float*)d_in[3];
    const float* bias = (const float*)d_in[4];
    float* out = (float*)d_out;

    boundary_kernel<<<(MROWS / 4 + 255) / 256, 256>>>(seg);
    wconv_kernel<<<32, 256>>>(W);
    pool_kernel<<<(NSEG + 3) / 4, 128>>>(lane);
    gemm_kernel<<<(NSEG_PAD + BM - 1) / BM, G_THREADS>>>(bias, out);
}

// round 10
// speedup vs baseline: 1.3686x; 1.0052x over previous
#include <cuda_runtime.h>
#include <cuda_fp16.h>
#include <math.h>
#include <stdint.h>

#define NSEG 50000
#define NSEG_PAD 50048
#define MROWS 800000
#define KDIM 256   // 2*D
#define ODIM 128

// Scratch (device globals zero-initialized -> padded rows of g_pooled_h are 0)
__device__ int    g_starts[NSEG + 1];
__device__ __half g_pooled_h[(long long)NSEG_PAD * KDIM];   // 25.6 MB
__device__ __half g_W_h[ODIM * KDIM];                       // 64 KB

// ---------------------------------------------------------------------------
// Kernel 1: segment boundary detection (unchanged, known-good).
// ---------------------------------------------------------------------------
__global__ void boundary_kernel(const void* __restrict__ segraw) {
    int t = blockIdx.x * blockDim.x + threadIdx.x;
    int base = t * 4;
    if (base >= MROWS) return;
    const int* s32 = (const int*)segraw;
    bool is64 = (s32[MROWS - 1] == 0);
    int v[5];
    if (is64) {
        const long long* s = (const long long*)segraw;
        v[0] = (base > 0) ? (int)s[base - 1] : -1;
        longlong2 a = *(const longlong2*)&s[base];
        longlong2 b = *(const longlong2*)&s[base + 2];
        v[1] = (int)a.x; v[2] = (int)a.y; v[3] = (int)b.x; v[4] = (int)b.y;
    } else {
        v[0] = (base > 0) ? s32[base - 1] : -1;
        int4 a = *(const int4*)&s32[base];
        v[1] = a.x; v[2] = a.y; v[3] = a.z; v[4] = a.w;
    }
#pragma unroll
    for (int j = 0; j < 4; ++j)
        if (v[j + 1] != v[j]) g_starts[v[j + 1]] = base + j;
    if (base == 0) g_starts[NSEG] = MROWS;
}

// ---------------------------------------------------------------------------
// Kernel 1b: W fp32 -> fp16 (one-time; unchanged).
// ---------------------------------------------------------------------------
__global__ void wconv_kernel(const float* __restrict__ W) {
    int t = blockIdx.x * blockDim.x + threadIdx.x;    // 0..8191
    float4 v = ((const float4*)W)[t];
    __half2 h01 = __float22half2_rn(make_float2(v.x, v.y));
    __half2 h23 = __float22half2_rn(make_float2(v.z, v.w));
    uint2 u;
    u.x = *(uint32_t*)&h01;
    u.y = *(uint32_t*)&h23;
    ((uint2*)g_W_h)[t] = u;
}

// ---------------------------------------------------------------------------
// Kernel 2: segmented max+mean pooling (unchanged from R9, near HBM floor).
// ---------------------------------------------------------------------------
__global__ void pool_kernel(const float* __restrict__ lane) {
    int warp = threadIdx.x >> 5;
    int lid  = threadIdx.x & 31;
    int n = blockIdx.x * 4 + warp;
    if (n >= NSEG) return;
    int start = g_starts[n];
    int len   = g_starts[n + 1] - start;

    const float4* p = reinterpret_cast<const float4*>(lane) + (long long)start * 32 + lid;

    float4 m0 = make_float4(-INFINITY, -INFINITY, -INFINITY, -INFINITY);
    float4 m1 = m0;
    float4 s0 = make_float4(0.f, 0.f, 0.f, 0.f);
    float4 s1 = s0;

    int r = 0;
    for (; r + 4 <= len; r += 4) {
        float4 v0 = __ldcs(p);
        float4 v1 = __ldcs(p + 32);
        float4 v2 = __ldcs(p + 64);
        float4 v3 = __ldcs(p + 96);
        p += 128;
        m0.x = fmaxf(m0.x, v0.x); s0.x += v0.x;
        m0.y = fmaxf(m0.y, v0.y); s0.y += v0.y;
        m0.z = fmaxf(m0.z, v0.z); s0.z += v0.z;
        m0.w = fmaxf(m0.w, v0.w); s0.w += v0.w;
        m1.x = fmaxf(m1.x, v1.x); s1.x += v1.x;
        m1.y = fmaxf(m1.y, v1.y); s1.y += v1.y;
        m1.z = fmaxf(m1.z, v1.z); s1.z += v1.z;
        m1.w = fmaxf(m1.w, v1.w); s1.w += v1.w;
        m0.x = fmaxf(m0.x, v2.x); s0.x += v2.x;
        m0.y = fmaxf(m0.y, v2.y); s0.y += v2.y;
        m0.z = fmaxf(m0.z, v2.z); s0.z += v2.z;
        m0.w = fmaxf(m0.w, v2.w); s0.w += v2.w;
        m1.x = fmaxf(m1.x, v3.x); s1.x += v3.x;
        m1.y = fmaxf(m1.y, v3.y); s1.y += v3.y;
        m1.z = fmaxf(m1.z, v3.z); s1.z += v3.z;
        m1.w = fmaxf(m1.w, v3.w); s1.w += v3.w;
    }
    for (; r < len; ++r) {
        float4 v = __ldcs(p);
        p += 32;
        m0.x = fmaxf(m0.x, v.x); s0.x += v.x;
        m0.y = fmaxf(m0.y, v.y); s0.y += v.y;
        m0.z = fmaxf(m0.z, v.z); s0.z += v.z;
        m0.w = fmaxf(m0.w, v.w); s0.w += v.w;
    }

    float4 mx, sm;
    mx.x = fmaxf(m0.x, m1.x); sm.x = s0.x + s1.x;
    mx.y = fmaxf(m0.y, m1.y); sm.y = s0.y + s1.y;
    mx.z = fmaxf(m0.z, m1.z); sm.z = s0.z + s1.z;
    mx.w = fmaxf(m0.w, m1.w); sm.w = s0.w + s1.w;

    float inv = 1.0f / (float)len;
    __half* row = g_pooled_h + (long long)n * KDIM;
    {
        __half2 h01 = __float22half2_rn(make_float2(mx.x, mx.y));
        __half2 h23 = __float22half2_rn(make_float2(mx.z, mx.w));
        uint2 u; u.x = *(uint32_t*)&h01; u.y = *(uint32_t*)&h23;
        ((uint2*)row)[lid] = u;
    }
    {
        __half2 h01 = __float22half2_rn(make_float2(sm.x * inv, sm.y * inv));
        __half2 h23 = __float22half2_rn(make_float2(sm.z * inv, sm.w * inv));
        uint2 u; u.x = *(uint32_t*)&h01; u.y = *(uint32_t*)&h23;
        ((uint2*)row)[32 + lid] = u;
    }
}

// ---------------------------------------------------------------------------
// Kernel 3: out = relu(pooled @ W^T + b), fp16 mma m16n8k16 + ldmatrix,
// 3-stage cp.async pipeline. CTA tile 64(M) x 128(N), BK=32 halves, 8 steps.
// Warps 2(M) x 4(N); warp tile 32x32 = 2 m-tiles x 4 n-tiles (32 acc regs).
// __launch_bounds__(256,3): 3 CTAs/SM (regs<=85, smem 46.6KB).
// ---------------------------------------------------------------------------
#define BM 64
#define BK 32          // halves per stage
#define SSTR 40        // smem row stride in halves (80B; ldmatrix conflict-free)
#define NSTAGE 3
#define NSTEPS (KDIM / BK)
#define G_THREADS 256

__device__ __forceinline__ void cpasync16(uint32_t dst, const void* src) {
    asm volatile("cp.async.cg.shared.global [%0], [%1], 16;" :: "r"(dst), "l"(src));
}
__device__ __forceinline__ void ldmx4(uint32_t& r0, uint32_t& r1, uint32_t& r2,
                                      uint32_t& r3, uint32_t addr) {
    asm volatile("ldmatrix.sync.aligned.m8n8.x4.shared.b16 {%0,%1,%2,%3}, [%4];"
                 : "=r"(r0), "=r"(r1), "=r"(r2), "=r"(r3) : "r"(addr));
}
__device__ __forceinline__ void mma_f16(float* d, uint32_t a0, uint32_t a1,
                                        uint32_t a2, uint32_t a3,
                                        uint32_t b0, uint32_t b1) {
    asm volatile(
        "mma.sync.aligned.m16n8k16.row.col.f32.f16.f16.f32 "
        "{%0,%1,%2,%3}, {%4,%5,%6,%7}, {%8,%9}, {%0,%1,%2,%3};"
        : "+f"(d[0]), "+f"(d[1]), "+f"(d[2]), "+f"(d[3])
        : "r"(a0), "r"(a1), "r"(a2), "r"(a3), "r"(b0), "r"(b1));
}

__global__ __launch_bounds__(G_THREADS, 3) void gemm_kernel(const float* __restrict__ bias,
                                                            float* __restrict__ out) {
    __shared__ __align__(16) __half As[NSTAGE][BM][SSTR];
    __shared__ __align__(16) __half Bs[NSTAGE][ODIM][SSTR];
    __shared__ float sbias[ODIM];

    const int tid  = threadIdx.x;
    const int wid  = tid >> 5;
    const int lane = tid & 31;
    const int g    = lane >> 2;
    const int l4   = lane & 3;
    const int warpM = wid >> 2;     // 0..1
    const int warpN = wid & 3;      // 0..3
    const int bm = blockIdx.x * BM;

    if (tid < ODIM) sbias[tid] = bias[tid];

    // Per-thread staging coordinates (A: 1 chunk, B: 2 chunks of 16B)
    const int arow = tid >> 2, ac8 = tid & 3;
    uint32_t as_base = (uint32_t)__cvta_generic_to_shared(&As[0][0][0]);
    uint32_t bs_base = (uint32_t)__cvta_generic_to_shared(&Bs[0][0][0]);

    // ldmatrix per-lane addressing
    const int jj = lane >> 3;
    const int rowoff = ((jj & 1) << 3) + (lane & 7);
    const int koff = (jj >> 1) << 3;
    uint32_t aoff[2], boff[2];
#pragma unroll
    for (int i = 0; i < 2; ++i)
        aoff[i] = ((warpM * 32 + i * 16 + rowoff) * SSTR + koff) * 2;
#pragma unroll
    for (int p = 0; p < 2; ++p)
        boff[p] = ((warpN * 32 + p * 16 + rowoff) * SSTR + koff) * 2;

    float acc[2][4][4];
#pragma unroll
    for (int i = 0; i < 2; ++i)
#pragma unroll
        for (int j = 0; j < 4; ++j)
#pragma unroll
            for (int c = 0; c < 4; ++c) acc[i][j][c] = 0.f;

    // Issue one stage's copies (global -> smem) and commit.
    auto issue_stage = [&](int step) {
        int s = step % NSTAGE;
        int kt = step * BK;
        cpasync16(as_base + (((s * BM + arow) * SSTR) + ac8 * 8) * 2,
                  &g_pooled_h[(long long)(bm + arow) * KDIM + kt + ac8 * 8]);
#pragma unroll
        for (int i = 0; i < 2; ++i) {
            int idx = tid + i * 256;
            int row = idx >> 2, c8 = idx & 3;
            cpasync16(bs_base + (((s * ODIM + row) * SSTR) + c8 * 8) * 2,
                      &g_W_h[row * KDIM + kt + c8 * 8]);
        }
        asm volatile("cp.async.commit_group;" ::: "memory");
    };

    issue_stage(0);
    issue_stage(1);

#pragma unroll 1
    for (int step = 0; step < NSTEPS; ++step) {
        // Wait for stage `step`'s group (keep <=1 newer group in flight).
        if (step < NSTEPS - 1) {
            asm volatile("cp.async.wait_group 1;" ::: "memory");
        } else {
            asm volatile("cp.async.wait_group 0;" ::: "memory");
        }
        __syncthreads();

        const int s = step % NSTAGE;
        uint32_t abase = as_base + s * BM * SSTR * 2;
        uint32_t bbase = bs_base + s * ODIM * SSTR * 2;
#pragma unroll
        for (int kk = 0; kk < BK / 16; ++kk) {
            const uint32_t kb = kk * 32;   // 16 halves = 32 bytes
            uint32_t a[2][4];
#pragma unroll
            for (int i = 0; i < 2; ++i)
                ldmx4(a[i][0], a[i][1], a[i][2], a[i][3], abase + aoff[i] + kb);
            uint32_t b[2][4];
#pragma unroll
            for (int p = 0; p < 2; ++p)
                ldmx4(b[p][0], b[p][1], b[p][2], b[p][3], bbase + boff[p] + kb);
#pragma unroll
            for (int i = 0; i < 2; ++i)
#pragma unroll
                for (int j = 0; j < 4; ++j) {
                    int p = j >> 1, o = j & 1;
                    mma_f16(acc[i][j], a[i][0], a[i][1], a[i][2], a[i][3],
                            b[p][o], b[p][o + 2]);
                }
        }
        __syncthreads();   // all warps done reading stage s before it is reused
        if (step + 2 < NSTEPS) issue_stage(step + 2);
    }

    // Epilogue: bias + relu, float2 stores.
#pragma unroll
    for (int i = 0; i < 2; ++i) {
        int r0 = bm + warpM * 32 + i * 16 + g;
#pragma unroll
        for (int j = 0; j < 4; ++j) {
            int col = warpN * 32 + j * 8 + 2 * l4;
            float bx = sbias[col], by = sbias[col + 1];
            if (r0 < NSEG) {
                float2 o;
                o.x = fmaxf(acc[i][j][0] + bx, 0.f);
                o.y = fmaxf(acc[i][j][1] + by, 0.f);
                *(float2*)&out[(long long)r0 * ODIM + col] = o;
            }
            if (r0 + 8 < NSEG) {
                float2 o;
                o.x = fmaxf(acc[i][j][2] + bx, 0.f);
                o.y = fmaxf(acc[i][j][3] + by, 0.f);
                *(float2*)&out[(long long)(r0 + 8) * ODIM + col] = o;
            }
        }
    }
}

// ---------------------------------------------------------------------------
// Inputs (metadata order): obs_encoding (unused), lane_encoding, same_obs_mask,
// W, b. Output: float32 [NSEG, ODIM].
// ---------------------------------------------------------------------------
extern "C" void kernel_launch(void* const* d_in, const int* in_sizes, int n_in,
                              void* d_out, int out_size) {
    const float* lane = (const float*)d_in[1];
    const void*  seg  = d_in[2];
    const float* W    = (const float*)d_in[3];
    const float* bias = (const float*)d_in[4];
    float* out = (float*)d_out;

    boundary_kernel<<<(MROWS / 4 + 255) / 256, 256>>>(seg);
    wconv_kernel<<<32, 256>>>(W);
    pool_kernel<<<(NSEG + 3) / 4, 128>>>(lane);
    gemm_kernel<<<NSEG_PAD / BM, G_THREADS>>>(bias, out);
}